// round 15
// baseline (speedup 1.0000x reference)
#include <cuda_runtime.h>
#include <cuda_fp16.h>
#include <cstdint>

#define N_TOK 131072
#define KC 256
#define DD 128
#define OFF_IDX  16777216
#define OFF_COMM 16908288
#define OFF_CBL  16908289
#define OFF_NCB  16908290
#define OFF_NC   16941058
#define OFF_NW   16941314

__device__ int   g_idx[N_TOK];
__device__ float g_ebp[(size_t)128 * KC * DD];
__device__ float g_esp[128 * KC];
__device__ float g_lp[1024];
__device__ float g_c2[KC];
__device__ float g_norm[KC];
__device__ __align__(16) unsigned short g_H[KC * DD];   // fp16(256*c), [code][dim]

__device__ __forceinline__ void mma16816(float* d, uint32_t a0, uint32_t a1, uint32_t a2, uint32_t a3,
                                         uint32_t b0, uint32_t b1) {
    asm volatile("mma.sync.aligned.m16n8k16.row.col.f32.f16.f16.f32 "
                 "{%0,%1,%2,%3},{%4,%5,%6,%7},{%8,%9},{%0,%1,%2,%3};"
                 : "+f"(d[0]), "+f"(d[1]), "+f"(d[2]), "+f"(d[3])
                 : "r"(a0), "r"(a1), "r"(a2), "r"(a3), "r"(b0), "r"(b1));
}
__device__ __forceinline__ void ldsm4(uint32_t* r, uint32_t addr) {
    asm volatile("ldmatrix.sync.aligned.m8n8.x4.shared.b16 {%0,%1,%2,%3},[%4];"
                 : "=r"(r[0]), "=r"(r[1]), "=r"(r[2]), "=r"(r[3]) : "r"(addr));
}
__device__ __forceinline__ uint32_t smem_u32(const void* p) {
    uint32_t a;
    asm("{ .reg .u64 t; cvta.to.shared.u64 t, %1; cvt.u32.u64 %0, t; }" : "=r"(a) : "l"(p));
    return a;
}
__device__ __forceinline__ uint32_t pkh(float a, float b) {
    __half2 h = __floats2half2_rn(a, b);
    return *reinterpret_cast<uint32_t*>(&h);
}

// smem byte offsets (assign kernel)
#define SM_ZS    0              // fp32 z tile [c][t], row stride 130 floats (66560 B)
#define SM_B     66560          // fp16(256*c) [256 codes][128 dim], row stride 272 B (69632 B)
#define SM_Z2    136192         // 128 f
#define SM_C2N   136704         // 256 f
#define SM_TB1   137728         // 128 f
#define SM_TB2   138240         // 128 f
#define SM_TK1   138752         // 128 i
#define SM_BD    139264         // 256 f
#define SM_BK    140288         // 256 i
#define SM_KF    141312         // 128 i
#define SM_LIST  141824         // 128 i
#define SM_NF    142336         // 1 i
#define SMEM_TOTAL 142340

// ---- kernel 0: fp16 scaled codebook + sequential c2 (proven arithmetic) ----
__global__ void prep_kernel(const float* __restrict__ cb) {
    int k = blockIdx.x, c = threadIdx.x;
    float v = cb[k * 128 + c];
    g_H[k * 128 + c] = __half_as_ushort(__float2half_rn(v * 256.0f));
    __shared__ float s[128];
    s[c] = v; __syncthreads();
    if (c == 0) {
        float a = 0.f;
        for (int i = 0; i < 128; i++) a = __fadd_rn(a, __fmul_rn(s[i], s[i]));
        g_c2[k] = a;
    }
}

// ---- kernel 1: fp16 HMMA distances + margin-guarded argmin + outputs ----
// grid 1024 (128-token tiles), block 256 (8 warps x 16 tokens).
__global__ void __launch_bounds__(256, 1)
assign_kernel(const float* __restrict__ z, const float* __restrict__ cb, float* __restrict__ out) {
    extern __shared__ char smc[];
    float* zs   = (float*)(smc + SM_ZS);
    float* z2s  = (float*)(smc + SM_Z2);
    float* c2s  = (float*)(smc + SM_C2N);
    float* tb1  = (float*)(smc + SM_TB1);
    float* tb2  = (float*)(smc + SM_TB2);
    int*   tk1  = (int*)  (smc + SM_TK1);
    float* bd   = (float*)(smc + SM_BD);
    int*   bk   = (int*)  (smc + SM_BK);
    int*   kfin = (int*)  (smc + SM_KF);
    int*   list = (int*)  (smc + SM_LIST);
    int*   nflag= (int*)  (smc + SM_NF);
    const uint32_t sb32 = smem_u32(smc);

    const int tid = threadIdx.x, w = tid >> 5, lane = tid & 31;
    const int g = lane >> 2, tig = lane & 3;
    const int m0 = w * 16;
    const int bx = blockIdx.x, b = bx >> 3, hw0 = (bx & 7) << 7;

    if (tid == 0) *nflag = 0;

    // codebook fp16 -> smem, row stride 272 B (68 u32/row, 64 data)
    { uint32_t* d1 = (uint32_t*)(smc + SM_B);
      const uint32_t* s1 = (const uint32_t*)g_H;
      for (int i = tid; i < 16384; i += 256) d1[(i >> 6) * 68 + (i & 63)] = s1[i]; }
    c2s[tid] = g_c2[tid];

    // z tile -> smem [c][t] (stride 130), coalesced on t
    { const float* zb = z + (size_t)b * 131072 + hw0;
      int t = tid & 127, ch = tid >> 7;
      #pragma unroll 8
      for (int it = 0; it < 64; it++) {
          int c = it * 2 + ch;
          zs[c * 130 + t] = zb[(size_t)c * 1024 + t];
      } }
    __syncthreads();

    // z2: sequential square-then-add (proven rounding order)
    if (tid < 128) {
        float s = 0.f;
        for (int c = 0; c < 128; c++) {
            float zv = zs[c * 130 + tid];
            s = __fadd_rn(s, __fmul_rn(zv, zv));
        }
        z2s[tid] = s;
    }
    __syncthreads();

    // A fragments fp16 (m16n8k16 row-major A), mapping validated in round 13
    uint32_t Af[32];
    #pragma unroll
    for (int ks = 0; ks < 8; ks++) {
        int c0 = ks * 16 + tig * 2;
        int r0 = m0 + g, r1 = m0 + g + 8;
        Af[ks * 4 + 0] = pkh(zs[c0 * 130 + r0],       zs[(c0 + 1) * 130 + r0]);
        Af[ks * 4 + 1] = pkh(zs[c0 * 130 + r1],       zs[(c0 + 1) * 130 + r1]);
        Af[ks * 4 + 2] = pkh(zs[(c0 + 8) * 130 + r0], zs[(c0 + 9) * 130 + r0]);
        Af[ks * 4 + 3] = pkh(zs[(c0 + 8) * 130 + r1], zs[(c0 + 9) * 130 + r1]);
    }

    // ldmatrix B addressing (validated round 13): B stored [n][k] -> col-major frag
    const uint32_t lrow = (lane & 7) + ((lane >> 4) << 3);
    const uint32_t lcol = ((lane >> 3) & 1) << 4;
    const uint32_t bbase = sb32 + SM_B + lrow * 272 + lcol;

    const float z2a = z2s[m0 + g], z2b = z2s[m0 + g + 8];

    // mainloop: 16 n-tiles of 16 codes; acc[8] live only per tile
    float b1r0 = 3.4e38f, b2r0 = 3.4e38f, b1r1 = 3.4e38f, b2r1 = 3.4e38f;
    int k1r0 = 0, k1r1 = 0;
    #pragma unroll 2
    for (int nt = 0; nt < 16; nt++) {
        float acc[8];
        #pragma unroll
        for (int i = 0; i < 8; i++) acc[i] = 0.f;
        uint32_t na = bbase + (uint32_t)(nt * 16) * 272u;
        #pragma unroll
        for (int ks = 0; ks < 8; ks++) {
            uint32_t B[4];
            ldsm4(B, na + (uint32_t)(ks * 32));
            mma16816(acc + 0, Af[ks*4+0], Af[ks*4+1], Af[ks*4+2], Af[ks*4+3], B[0], B[1]);
            mma16816(acc + 4, Af[ks*4+0], Af[ks*4+1], Af[ks*4+2], Af[ks*4+3], B[2], B[3]);
        }
        // distances: acc holds 256*dot -> -2*dot = -acc/128
        #pragma unroll
        for (int h = 0; h < 2; h++) {
            int nb = nt * 16 + h * 8 + tig * 2;
            int ai = h * 4;
            float c20 = c2s[nb], c21 = c2s[nb + 1];
            float d;
            d = __fadd_rn(__fadd_rn(z2a, -0.0078125f * acc[ai + 0]), c20);
            if (d < b1r0) { b2r0 = b1r0; b1r0 = d; k1r0 = nb; } else if (d < b2r0) b2r0 = d;
            d = __fadd_rn(__fadd_rn(z2a, -0.0078125f * acc[ai + 1]), c21);
            if (d < b1r0) { b2r0 = b1r0; b1r0 = d; k1r0 = nb + 1; } else if (d < b2r0) b2r0 = d;
            d = __fadd_rn(__fadd_rn(z2b, -0.0078125f * acc[ai + 2]), c20);
            if (d < b1r1) { b2r1 = b1r1; b1r1 = d; k1r1 = nb; } else if (d < b2r1) b2r1 = d;
            d = __fadd_rn(__fadd_rn(z2b, -0.0078125f * acc[ai + 3]), c21);
            if (d < b1r1) { b2r1 = b1r1; b1r1 = d; k1r1 = nb + 1; } else if (d < b2r1) b2r1 = d;
        }
    }
    // quad reduce (offsets 1,2), lexicographic ties (validated round 13)
    #pragma unroll
    for (int off = 1; off <= 2; off <<= 1) {
        float ob1, ob2; int ok1;
        ob1 = __shfl_down_sync(0xffffffffu, b1r0, off);
        ok1 = __shfl_down_sync(0xffffffffu, k1r0, off);
        ob2 = __shfl_down_sync(0xffffffffu, b2r0, off);
        if (ob1 < b1r0 || (ob1 == b1r0 && ok1 < k1r0)) { b2r0 = fminf(b1r0, ob2); b1r0 = ob1; k1r0 = ok1; }
        else b2r0 = fminf(b2r0, ob1);
        ob1 = __shfl_down_sync(0xffffffffu, b1r1, off);
        ok1 = __shfl_down_sync(0xffffffffu, k1r1, off);
        ob2 = __shfl_down_sync(0xffffffffu, b2r1, off);
        if (ob1 < b1r1 || (ob1 == b1r1 && ok1 < k1r1)) { b2r1 = fminf(b1r1, ob2); b1r1 = ob1; k1r1 = ok1; }
        else b2r1 = fminf(b2r1, ob1);
    }
    if (tig == 0) {
        tb1[m0 + g] = b1r0; tk1[m0 + g] = k1r0; tb2[m0 + g] = b2r0;
        tb1[m0 + g + 8] = b1r1; tk1[m0 + g + 8] = k1r1; tb2[m0 + g + 8] = b2r1;
    }
    __syncthreads();

    // margin check (fp16 single-product error 6sigma ~ 1.7e-4 < 4e-4)
    if (tid < 128) {
        kfin[tid] = tk1[tid];
        float margin = tb2[tid] - tb1[tid];
        if (!(margin > 4e-4f)) { int p = atomicAdd(nflag, 1); list[p] = tid; }
    }
    __syncthreads();

    // exact fp32 fallback (round-2-proven arithmetic, lexicographic ties)
    int nf = *nflag;
    for (int f = 0; f < nf; f++) {
        int tf = list[f];
        const float4* crow = (const float4*)(cb + (size_t)tid * 128);
        float dot = 0.f;
        #pragma unroll 8
        for (int i = 0; i < 32; i++) {
            float4 q = __ldg(crow + i);
            dot = __fmaf_rn(zs[(4 * i + 0) * 130 + tf], q.x, dot);
            dot = __fmaf_rn(zs[(4 * i + 1) * 130 + tf], q.y, dot);
            dot = __fmaf_rn(zs[(4 * i + 2) * 130 + tf], q.z, dot);
            dot = __fmaf_rn(zs[(4 * i + 3) * 130 + tf], q.w, dot);
        }
        float d = __fadd_rn(__fadd_rn(z2s[tf], -2.f * dot), c2s[tid]);
        bd[tid] = d; bk[tid] = tid;
        __syncthreads();
        for (int o = 128; o; o >>= 1) {
            if (tid < o) {
                float od = bd[tid + o]; int ok = bk[tid + o];
                if (od < bd[tid] || (od == bd[tid] && ok < bk[tid])) { bd[tid] = od; bk[tid] = ok; }
            }
            __syncthreads();
        }
        if (tid == 0) kfin[tf] = bk[0];
        __syncthreads();
    }

    // outputs: idx, quantized (straight-through), loss partial (validated)
    float ls = 0.f;
    if (tid < 128) {
        int n = b * 1024 + hw0 + tid;
        int fk = kfin[tid];
        g_idx[n] = fk; out[OFF_IDX + n] = (float)fk;
        const float4* crow = (const float4*)(cb + (size_t)fk * 128);
        float* ob = out + (size_t)b * 131072 + hw0 + tid;
        #pragma unroll 4
        for (int i = 0; i < 32; i++) {
            float4 q = __ldg(crow + i);
            float zv, df;
            zv = zs[(4 * i + 0) * 130 + tid]; df = __fsub_rn(zv, q.x); ls = __fmaf_rn(df, df, ls);
            ob[(size_t)(4 * i + 0) * 1024] = __fadd_rn(zv, __fsub_rn(q.x, zv));
            zv = zs[(4 * i + 1) * 130 + tid]; df = __fsub_rn(zv, q.y); ls = __fmaf_rn(df, df, ls);
            ob[(size_t)(4 * i + 1) * 1024] = __fadd_rn(zv, __fsub_rn(q.y, zv));
            zv = zs[(4 * i + 2) * 130 + tid]; df = __fsub_rn(zv, q.z); ls = __fmaf_rn(df, df, ls);
            ob[(size_t)(4 * i + 2) * 1024] = __fadd_rn(zv, __fsub_rn(q.z, zv));
            zv = zs[(4 * i + 3) * 130 + tid]; df = __fsub_rn(zv, q.w); ls = __fmaf_rn(df, df, ls);
            ob[(size_t)(4 * i + 3) * 1024] = __fadd_rn(zv, __fsub_rn(q.w, zv));
        }
    }
    bd[tid] = ls; __syncthreads();
    #pragma unroll
    for (int o = 128; o; o >>= 1) { if (tid < o) bd[tid] += bd[tid + o]; __syncthreads(); }
    if (tid == 0) g_lp[bx] = bd[0];
}

// ---- kernel 2: segment-sum partials via smem atomics (validated round 14) ----
__global__ void __launch_bounds__(128, 1)
aggregate_kernel(const float* __restrict__ z) {
    extern __shared__ float sm[];
    float* acc  = sm;
    float* cnt  = sm + 32768;
    int*   sidx = (int*)(sm + 33024);
    const int tid = threadIdx.x, b = blockIdx.x;

    { float4 zf = make_float4(0.f, 0.f, 0.f, 0.f);
      float4* a4 = (float4*)acc;
      #pragma unroll
      for (int i = tid; i < 8192; i += 128) a4[i] = zf; }
    cnt[tid] = 0.f; cnt[tid + 128] = 0.f;
    for (int i = tid; i < 1024; i += 128) sidx[i] = g_idx[b * 1024 + i];
    __syncthreads();

    const float* zc = z + (size_t)b * 131072 + (size_t)tid * 1024;
    float* ac = acc + tid;
    #pragma unroll 4
    for (int t = 0; t < 1024; t += 4) {
        float4 v = *(const float4*)(zc + t);
        atomicAdd(ac + sidx[t]     * 128, v.x);
        atomicAdd(ac + sidx[t + 1] * 128, v.y);
        atomicAdd(ac + sidx[t + 2] * 128, v.z);
        atomicAdd(ac + sidx[t + 3] * 128, v.w);
    }
    #pragma unroll
    for (int j = 0; j < 8; j++) atomicAdd(cnt + sidx[tid * 8 + j], 1.0f);
    __syncthreads();

    { float4* a4 = (float4*)acc; float4* o4 = (float4*)(g_ebp + (size_t)b * 32768);
      for (int i = tid; i < 8192; i += 128) o4[i] = a4[i]; }
    g_esp[b * KC + tid] = cnt[tid];
    g_esp[b * KC + tid + 128] = cnt[tid + 128];
}

// ---- kernel 3: reduce partials -> new_weight / new_count (validated round 14) ----
__global__ void fin1_kernel(const float* __restrict__ emaw, const float* __restrict__ emac,
                            float* __restrict__ out) {
    __shared__ float part[256];
    __shared__ float red[128];
    int k = blockIdx.x, tid = threadIdx.x;
    int c = tid & 127, h = tid >> 7;
    float wv = 0.f;
    #pragma unroll 16
    for (int b = h * 64; b < h * 64 + 64; b++) wv += g_ebp[(size_t)b * 32768 + k * DD + c];
    part[tid] = wv;
    if (h == 0) red[c] = g_esp[c * KC + k];
    __syncthreads();
    if (h == 0)
        out[OFF_NW + k * DD + c] = 0.99f * emaw[k * DD + c] + 0.01f * (part[c] + part[c + 128]);
    #pragma unroll
    for (int o = 64; o; o >>= 1) { if (tid < o) red[tid] += red[tid + o]; __syncthreads(); }
    if (tid == 0) out[OFF_NC + k] = 0.99f * emac[k] + 0.01f * red[0];
}

// ---- kernel 4: n, normalized_count, losses (grid-1024 g_lp) ----
__global__ void fin2_kernel(float* __restrict__ out) {
    __shared__ float red[256];
    int tid = threadIdx.x;
    float v = out[OFF_NC + tid];
    red[tid] = v; __syncthreads();
    #pragma unroll
    for (int o = 128; o; o >>= 1) { if (tid < o) red[tid] += red[tid + o]; __syncthreads(); }
    float n = red[0];
    g_norm[tid] = __fmul_rn(__fdiv_rn(__fadd_rn(v, 1e-5f), __fadd_rn(n, 0.00256f)), n);
    float ls = 0.f;
    for (int i = 0; i < 4; i++) ls += g_lp[tid * 4 + i];
    red[tid] = ls; __syncthreads();
    #pragma unroll
    for (int o = 128; o; o >>= 1) { if (tid < o) red[tid] += red[tid + o]; __syncthreads(); }
    if (tid == 0) {
        float m = red[0] / 16777216.0f;
        out[OFF_COMM] = 0.25f * m;
        out[OFF_CBL]  = m;
    }
}

// ---- kernel 5: new_codebook ----
__global__ void fin3_kernel(float* __restrict__ out) {
    int i = blockIdx.x * 256 + threadIdx.x;
    out[OFF_NCB + i] = __fdiv_rn(out[OFF_NW + i], g_norm[i >> 7]);
}

extern "C" void kernel_launch(void* const* d_in, const int* in_sizes, int n_in,
                              void* d_out, int out_size) {
    const float* z    = (const float*)d_in[0];
    const float* cb   = (const float*)d_in[1];
    const float* emac = (const float*)d_in[2];
    const float* emaw = (const float*)d_in[3];
    float* out = (float*)d_out;

    cudaFuncSetAttribute(assign_kernel,    cudaFuncAttributeMaxDynamicSharedMemorySize, SMEM_TOTAL);
    cudaFuncSetAttribute(aggregate_kernel, cudaFuncAttributeMaxDynamicSharedMemorySize, 136192);

    prep_kernel<<<256, 128>>>(cb);
    assign_kernel<<<1024, 256, SMEM_TOTAL>>>(z, cb, out);
    aggregate_kernel<<<128, 128, 136192>>>(z);
    fin1_kernel<<<256, 256>>>(emaw, emac, out);
    fin2_kernel<<<1, 256>>>(out);
    fin3_kernel<<<128, 256>>>(out);
}

// round 17
// speedup vs baseline: 1.2295x; 1.2295x over previous
#include <cuda_runtime.h>
#include <cstdint>

#define N_TOK 131072
#define KC 256
#define DD 128
#define OFF_IDX  16777216
#define OFF_COMM 16908288
#define OFF_CBL  16908289
#define OFF_NCB  16908290
#define OFF_NC   16941058
#define OFF_NW   16941314

__device__ int   g_idx[N_TOK];
__device__ float g_ebp[(size_t)128 * KC * DD];   // per-b enc_batch partials
__device__ float g_esp[128 * KC];                // per-b enc_sum partials
__device__ float g_lp[2048];                     // per-block loss partials
__device__ float g_cbT[DD * KC];                 // codebook transposed [c][k]
__device__ float g_c2[KC];
__device__ float g_norm[KC];

__device__ __forceinline__ void fma2(unsigned long long& d, unsigned long long a, unsigned long long b) {
    asm("fma.rn.f32x2 %0,%1,%2,%0;" : "+l"(d) : "l"(a), "l"(b));
}
__device__ __forceinline__ void upk(unsigned long long v, float& a, float& b) {
    asm("mov.b64 {%0,%1},%2;" : "=f"(a), "=f"(b) : "l"(v));
}
__device__ __forceinline__ unsigned long long pk2(float f) {
    unsigned long long r; asm("mov.b64 %0,{%1,%1};" : "=l"(r) : "f"(f)); return r;
}

// ---- kernel 0: transpose codebook + per-code squared norm (validated) ----
__global__ void prep_kernel(const float* __restrict__ cb) {
    int k = blockIdx.x, c = threadIdx.x;
    __shared__ float s[DD];
    float v = cb[k * DD + c];
    g_cbT[c * KC + k] = v; s[c] = v;
    __syncthreads();
    if (c == 0) {
        float acc = 0.f;
        for (int i = 0; i < DD; i++) acc = __fadd_rn(acc, __fmul_rn(s[i], s[i]));
        g_c2[k] = acc;
    }
}

// ---- kernel 1: fp32 FFMA2 distances + argmin + quantized + idx + loss ----
// (R14 assign_v3, validated rel_err 3.0e-7) grid 2048, block 256, smem 166400B.
__global__ void __launch_bounds__(256, 1)
assign_kernel(const float* __restrict__ z, float* __restrict__ out) {
    extern __shared__ float sm[];
    float* cbs = sm;                 // 32768
    float* zsc = sm + 32768;         // 8192  [c][t] stride 64
    float* c2s = sm + 40960;         // 256
    float* z2s = c2s + 256;          // 64
    float* red = z2s + 64;           // 256
    int*  idxs = (int*)(red + 256);  // 64

    const int tid = threadIdx.x, T = blockIdx.x, b = T >> 4, h2 = T & 15;
    const float* zb = z + (size_t)b * 131072 + h2 * 64;

    { const float4* s4 = (const float4*)g_cbT; float4* d4 = (float4*)cbs;
      #pragma unroll
      for (int i = 0; i < 32; i++) d4[tid + i * 256] = s4[tid + i * 256]; }
    c2s[tid] = g_c2[tid];

    #pragma unroll
    for (int it = 0; it < 8; it++) {
        int c = it * 16 + (tid >> 4), p = tid & 15;
        float4 v = *(const float4*)(zb + (size_t)c * 1024 + p * 4);
        *(float4*)(zsc + c * 64 + p * 4) = v;
    }
    __syncthreads();

    if (tid < 64) {   // z2: sequential square-then-add (proven rounding order)
        float s = 0.f;
        for (int c = 0; c < DD; c++) {
            float zv = zsc[c * 64 + tid];
            s = __fadd_rn(s, __fmul_rn(zv, zv));
        }
        z2s[tid] = s;
    }
    __syncthreads();

    const int w = tid >> 5, l = tid & 31, t0 = w * 8;
    unsigned long long A0[8], A1[8], B0[8], B1[8];
    #pragma unroll
    for (int t = 0; t < 8; t++) { A0[t] = 0; A1[t] = 0; B0[t] = 0; B1[t] = 0; }
    const float* cbp = cbs + 4 * l;
    #pragma unroll 4
    for (int c = 0; c < 128; c++) {
        ulonglong2 ca  = *(const ulonglong2*)(cbp + (c << 8));
        ulonglong2 cb2 = *(const ulonglong2*)(cbp + (c << 8) + 128);
        float4 zlo = *(const float4*)(zsc + (c << 6) + t0);      // broadcast
        float4 zhi = *(const float4*)(zsc + (c << 6) + t0 + 4);  // broadcast
        unsigned long long zz;
        zz = pk2(zlo.x);
        fma2(A0[0], zz, ca.x); fma2(A1[0], zz, ca.y); fma2(B0[0], zz, cb2.x); fma2(B1[0], zz, cb2.y);
        zz = pk2(zlo.y);
        fma2(A0[1], zz, ca.x); fma2(A1[1], zz, ca.y); fma2(B0[1], zz, cb2.x); fma2(B1[1], zz, cb2.y);
        zz = pk2(zlo.z);
        fma2(A0[2], zz, ca.x); fma2(A1[2], zz, ca.y); fma2(B0[2], zz, cb2.x); fma2(B1[2], zz, cb2.y);
        zz = pk2(zlo.w);
        fma2(A0[3], zz, ca.x); fma2(A1[3], zz, ca.y); fma2(B0[3], zz, cb2.x); fma2(B1[3], zz, cb2.y);
        zz = pk2(zhi.x);
        fma2(A0[4], zz, ca.x); fma2(A1[4], zz, ca.y); fma2(B0[4], zz, cb2.x); fma2(B1[4], zz, cb2.y);
        zz = pk2(zhi.y);
        fma2(A0[5], zz, ca.x); fma2(A1[5], zz, ca.y); fma2(B0[5], zz, cb2.x); fma2(B1[5], zz, cb2.y);
        zz = pk2(zhi.z);
        fma2(A0[6], zz, ca.x); fma2(A1[6], zz, ca.y); fma2(B0[6], zz, cb2.x); fma2(B1[6], zz, cb2.y);
        zz = pk2(zhi.w);
        fma2(A0[7], zz, ca.x); fma2(A1[7], zz, ca.y); fma2(B0[7], zz, cb2.x); fma2(B1[7], zz, cb2.y);
    }

    // d = (z2 - 2*zc) + c2, proven op order; strict < => first-index ties
    #pragma unroll
    for (int t = 0; t < 8; t++) {
        float z2v = z2s[t0 + t], lo, hi, d, best; int bi;
        upk(A0[t], lo, hi);
        best = __fadd_rn(__fadd_rn(z2v, -2.f * lo), c2s[4 * l]);      bi = 4 * l;
        d = __fadd_rn(__fadd_rn(z2v, -2.f * hi), c2s[4 * l + 1]);     if (d < best) { best = d; bi = 4 * l + 1; }
        upk(A1[t], lo, hi);
        d = __fadd_rn(__fadd_rn(z2v, -2.f * lo), c2s[4 * l + 2]);     if (d < best) { best = d; bi = 4 * l + 2; }
        d = __fadd_rn(__fadd_rn(z2v, -2.f * hi), c2s[4 * l + 3]);     if (d < best) { best = d; bi = 4 * l + 3; }
        upk(B0[t], lo, hi);
        d = __fadd_rn(__fadd_rn(z2v, -2.f * lo), c2s[128 + 4 * l]);   if (d < best) { best = d; bi = 128 + 4 * l; }
        d = __fadd_rn(__fadd_rn(z2v, -2.f * hi), c2s[129 + 4 * l]);   if (d < best) { best = d; bi = 129 + 4 * l; }
        upk(B1[t], lo, hi);
        d = __fadd_rn(__fadd_rn(z2v, -2.f * lo), c2s[130 + 4 * l]);   if (d < best) { best = d; bi = 130 + 4 * l; }
        d = __fadd_rn(__fadd_rn(z2v, -2.f * hi), c2s[131 + 4 * l]);   if (d < best) { best = d; bi = 131 + 4 * l; }
        #pragma unroll
        for (int off = 16; off; off >>= 1) {
            float ob = __shfl_down_sync(0xffffffffu, best, off);
            int   oi = __shfl_down_sync(0xffffffffu, bi, off);
            if (ob < best || (ob == best && oi < bi)) { best = ob; bi = oi; }
        }
        if (l == 0) idxs[t0 + t] = bi;
    }
    __syncthreads();

    if (tid < 64) {
        int n = T * 64 + tid, k = idxs[tid];
        g_idx[n] = k; out[OFF_IDX + n] = (float)k;
    }
    float ls = 0.f;
    { int q = tid >> 6, tl = tid & 63, k = idxs[tl];
      float* ob = out + (size_t)b * 131072 + h2 * 64 + tl;
      #pragma unroll
      for (int i = 0; i < 32; i++) {
          int c = i * 4 + q;
          float qv = cbs[c * 256 + k], zv = zsc[c * 64 + tl];
          float df = __fsub_rn(zv, qv);
          ls = __fmaf_rn(df, df, ls);
          ob[(size_t)c * 1024] = __fadd_rn(zv, __fsub_rn(qv, zv));  // straight-through value
      } }
    red[tid] = ls; __syncthreads();
    #pragma unroll
    for (int o = 128; o; o >>= 1) { if (tid < o) red[tid] += red[tid + o]; __syncthreads(); }
    if (tid == 0) g_lp[T] = red[0];
}

// ---- kernel 2: segment-sum partials, dedup-batched smem RMW (R13-validated) ----
// grid 128 (one b, 1024 tokens), block 128 (thread = channel c). smem 145024 B.
__global__ void __launch_bounds__(128, 1)
aggregate_kernel(const float* __restrict__ z) {
    extern __shared__ float sm[];
    float* acc  = sm;                       // 259*128 = 33152 floats
    int*   sidx = (int*)(sm + 33152);       // 1024 ints
    float* cnt8 = sm + 33152 + 1024;        // 8*260 = 2080 floats
    const int tid = threadIdx.x, b = blockIdx.x;

    for (int i = tid; i < 33152; i += 128) acc[i] = 0.f;
    for (int i = tid; i < 2080; i += 128) cnt8[i] = 0.f;
    for (int i = tid; i < 1024; i += 128) sidx[i] = g_idx[b * 1024 + i];
    __syncthreads();

    const float* zc = z + (size_t)b * 131072 + (size_t)tid * 1024;
    float* ac = acc + tid;
    #pragma unroll 4
    for (int t = 0; t < 1024; t += 4) {
        float4 v = *(const float4*)(zc + t);
        int k0 = sidx[t], k1 = sidx[t + 1], k2 = sidx[t + 2], k3 = sidx[t + 3];
        float v0 = v.x, v1 = v.y, v2 = v.z, v3 = v.w;
        if (k1 == k0) { v0 += v1; k1 = 256; }
        if (k2 == k0) { v0 += v2; k2 = 257; } else if (k2 == k1) { v1 += v2; k2 = 257; }
        if (k3 == k0) { v0 += v3; k3 = 258; } else if (k3 == k1) { v1 += v3; k3 = 258; }
        else if (k3 == k2) { v2 += v3; k3 = 258; }
        ac[k0 * 128] += v0; ac[k1 * 128] += v1; ac[k2 * 128] += v2; ac[k3 * 128] += v3;
    }
    if (tid < 8) {
        float* my = cnt8 + tid * 260;
        #pragma unroll 2
        for (int t = tid * 128; t < tid * 128 + 128; t += 4) {
            int k0 = sidx[t], k1 = sidx[t + 1], k2 = sidx[t + 2], k3 = sidx[t + 3];
            float c0 = 1.f, c1 = 1.f, c2 = 1.f, c3 = 1.f;
            if (k1 == k0) { c0 += c1; k1 = 256; }
            if (k2 == k0) { c0 += c2; k2 = 257; } else if (k2 == k1) { c1 += c2; k2 = 257; }
            if (k3 == k0) { c0 += c3; k3 = 258; } else if (k3 == k1) { c1 += c3; k3 = 258; }
            else if (k3 == k2) { c2 += c3; k3 = 258; }
            my[k0] += c0; my[k1] += c1; my[k2] += c2; my[k3] += c3;
        }
    }
    __syncthreads();
    for (int i = tid; i < 32768; i += 128) g_ebp[(size_t)b * 32768 + i] = acc[i];
    for (int k = tid; k < 256; k += 128) {
        float s = 0.f;
        #pragma unroll
        for (int j = 0; j < 8; j++) s += cnt8[j * 260 + k];
        g_esp[b * KC + k] = s;
    }
}

// ---- kernel 3: reduce partials -> new_weight / new_count (R14-validated) ----
__global__ void fin1_kernel(const float* __restrict__ emaw, const float* __restrict__ emac,
                            float* __restrict__ out) {
    __shared__ float part[256];
    __shared__ float red[128];
    int k = blockIdx.x, tid = threadIdx.x;
    int c = tid & 127, h = tid >> 7;
    float wv = 0.f;
    #pragma unroll 16
    for (int b = h * 64; b < h * 64 + 64; b++) wv += g_ebp[(size_t)b * 32768 + k * DD + c];
    part[tid] = wv;
    if (h == 0) red[c] = g_esp[c * KC + k];
    __syncthreads();
    if (h == 0)
        out[OFF_NW + k * DD + c] = 0.99f * emaw[k * DD + c] + 0.01f * (part[c] + part[c + 128]);
    #pragma unroll
    for (int o = 64; o; o >>= 1) { if (tid < o) red[tid] += red[tid + o]; __syncthreads(); }
    if (tid == 0) out[OFF_NC + k] = 0.99f * emac[k] + 0.01f * red[0];
}

// ---- kernel 4: n, normalized_count, losses (2048 loss partials) ----
__global__ void fin2_kernel(float* __restrict__ out) {
    __shared__ float red[256];
    int tid = threadIdx.x;
    float v = out[OFF_NC + tid];
    red[tid] = v; __syncthreads();
    #pragma unroll
    for (int o = 128; o; o >>= 1) { if (tid < o) red[tid] += red[tid + o]; __syncthreads(); }
    float n = red[0];
    g_norm[tid] = __fmul_rn(__fdiv_rn(__fadd_rn(v, 1e-5f), __fadd_rn(n, 0.00256f)), n);
    float ls = 0.f;
    for (int i = 0; i < 8; i++) ls += g_lp[tid * 8 + i];
    red[tid] = ls; __syncthreads();
    #pragma unroll
    for (int o = 128; o; o >>= 1) { if (tid < o) red[tid] += red[tid + o]; __syncthreads(); }
    if (tid == 0) {
        float m = red[0] / 16777216.0f;
        out[OFF_COMM] = 0.25f * m;
        out[OFF_CBL]  = m;
    }
}

// ---- kernel 5: new_codebook ----
__global__ void fin3_kernel(float* __restrict__ out) {
    int i = blockIdx.x * 256 + threadIdx.x;
    out[OFF_NCB + i] = __fdiv_rn(out[OFF_NW + i], g_norm[i >> 7]);
}

extern "C" void kernel_launch(void* const* d_in, const int* in_sizes, int n_in,
                              void* d_out, int out_size) {
    const float* z    = (const float*)d_in[0];
    const float* cb   = (const float*)d_in[1];
    const float* emac = (const float*)d_in[2];
    const float* emaw = (const float*)d_in[3];
    float* out = (float*)d_out;

    cudaFuncSetAttribute(assign_kernel,    cudaFuncAttributeMaxDynamicSharedMemorySize, 166400);
    cudaFuncSetAttribute(aggregate_kernel, cudaFuncAttributeMaxDynamicSharedMemorySize, 145024);

    prep_kernel<<<256, 128>>>(cb);
    assign_kernel<<<2048, 256, 166400>>>(z, out);
    aggregate_kernel<<<128, 128, 145024>>>(z);
    fin1_kernel<<<256, 256>>>(emaw, emac, out);
    fin2_kernel<<<1, 256>>>(out);
    fin3_kernel<<<128, 256>>>(out);
}